// round 17
// baseline (speedup 1.0000x reference)
#include <cuda_runtime.h>
#include <cuda_fp16.h>
#include <math.h>
#include <math_constants.h>
#include <stdint.h>

#define NN 20000
#define EE 160000
#define DD 128
#define NFUSE 1664   // 512(q)+512(k)+512(v)+128(skip)

// ---------------- scratch (static device globals; no allocation) ----------------
__device__ __half g_qkv[NN * 1536];    // q|k|v fp16, row stride 1536
__device__ float  g_skip[NN * DD];     // skip fp32
__device__ __half g_toutf[NN * DD];    // temporal out fp16
__device__ float g_x2[NN * DD];
__device__ float g_bias_f[NFUSE];
__device__ float g_wc[128 * 128];      // composed temporal weight Wo@Wv
__device__ float g_bc[128];            // composed temporal bias Wo@bv+bo
// CSR scratch
__device__ int g_deg[NN];
__device__ int g_rowptr[NN + 1];
__device__ int g_cursor[NN];
__device__ int g_blocksum[32];
__device__ int g_ssrc[EE];

// fp16 operand buffers
__device__ __half g_xf[NN * DD];
__device__ __half g_tef[NN * DD];
__device__ __half g_x2f[NN * DD];
__device__ __half g_hf[NN * 512];
__device__ __half g_wf[NFUSE * 128];
__device__ __half g_wcf[128 * 128];
__device__ __half g_w1f[512 * 128];
__device__ __half g_w2f[128 * 512];

// ---------------- helpers ----------------
__device__ __forceinline__ void mma_f16(float* c, const uint32_t* a, const uint32_t* b) {
    asm volatile(
        "mma.sync.aligned.m16n8k16.row.col.f32.f16.f16.f32 "
        "{%0,%1,%2,%3}, {%4,%5,%6,%7}, {%8,%9}, {%0,%1,%2,%3};"
        : "+f"(c[0]), "+f"(c[1]), "+f"(c[2]), "+f"(c[3])
        : "r"(a[0]), "r"(a[1]), "r"(a[2]), "r"(a[3]), "r"(b[0]), "r"(b[1]));
}

__device__ __forceinline__ void ldsm_x4(uint32_t& r0, uint32_t& r1, uint32_t& r2,
                                        uint32_t& r3, uint32_t addr) {
    asm volatile("ldmatrix.sync.aligned.m8n8.x4.shared.b16 {%0,%1,%2,%3}, [%4];"
                 : "=r"(r0), "=r"(r1), "=r"(r2), "=r"(r3) : "r"(addr));
}

__device__ __forceinline__ void cp16(uint32_t dst, const void* src) {
    asm volatile("cp.async.cg.shared.global [%0], [%1], 16;" :: "r"(dst), "l"(src));
}

__device__ __forceinline__ float4 ln_core(float4 vv, int lane,
                                          const float* __restrict__ g,
                                          const float* __restrict__ b) {
    float sum = vv.x + vv.y + vv.z + vv.w;
    float sq = vv.x * vv.x + vv.y * vv.y + vv.z * vv.z + vv.w * vv.w;
#pragma unroll
    for (int o = 16; o > 0; o >>= 1) {
        sum += __shfl_xor_sync(0xffffffffu, sum, o);
        sq  += __shfl_xor_sync(0xffffffffu, sq, o);
    }
    float mu = sum * (1.f / 128.f);
    float var = sq * (1.f / 128.f) - mu * mu;
    float rstd = rsqrtf(var + 1e-5f);
    float4 gv = reinterpret_cast<const float4*>(g)[lane];
    float4 bv = reinterpret_cast<const float4*>(b)[lane];
    float4 o;
    o.x = (vv.x - mu) * rstd * gv.x + bv.x;
    o.y = (vv.y - mu) * rstd * gv.y + bv.y;
    o.z = (vv.z - mu) * rstd * gv.z + bv.z;
    o.w = (vv.w - mu) * rstd * gv.w + bv.w;
    return o;
}

// ---------------- setup + temporal compose, one launch ----------------
// blocks [0,128): compose row blockIdx.x of Wc = Wo@Wv, bc = Wo@bv+bo
// blocks [128, 128+NB): deg=0 + bias concat
__global__ void setup_compose(const float* __restrict__ wo,
                              const float* __restrict__ wv,
                              const float* __restrict__ bv,
                              const float* __restrict__ bo,
                              const float* a, const float* b,
                              const float* c, const float* d) {
    if (blockIdx.x < 128) {
        int i = blockIdx.x;
        int j = threadIdx.x;
        if (j >= 128) return;
        __shared__ float wo_s[128];
        __shared__ float bs[4];
        wo_s[j] = wo[i * 128 + j];
        __syncthreads();
        float sum = 0.f;
#pragma unroll 8
        for (int k = 0; k < 128; k++) sum += wo_s[k] * wv[k * 128 + j];
        g_wc[i * 128 + j] = sum;
        float bb = wo_s[j] * bv[j];
#pragma unroll
        for (int o = 16; o > 0; o >>= 1) bb += __shfl_xor_sync(0xffffffffu, bb, o);
        if ((j & 31) == 0) bs[j >> 5] = bb;
        __syncthreads();
        if (j == 0) g_bc[i] = bs[0] + bs[1] + bs[2] + bs[3] + bo[i];
    } else {
        int i = (blockIdx.x - 128) * 256 + threadIdx.x;
        if (i < NN) g_deg[i] = 0;
        if (i < 512) g_bias_f[i] = a[i];
        else if (i < 1024) g_bias_f[i] = b[i - 512];
        else if (i < 1536) g_bias_f[i] = c[i - 1024];
        else if (i < NFUSE) g_bias_f[i] = d[i - 1536];
    }
}

// ---------------- batched fp32 -> fp16 conversion ----------------
struct AJ { const float* s; __half* d; int n4; };
struct AJs { AJ j[9]; };
__global__ void conv_a(AJs jobs) {
    AJ job = jobs.j[blockIdx.y];
    int stride = gridDim.x * blockDim.x;
    for (int i = blockIdx.x * blockDim.x + threadIdx.x; i < job.n4; i += stride) {
        float4 v = reinterpret_cast<const float4*>(job.s)[i];
        reinterpret_cast<__half2*>(job.d)[2 * i]     = __floats2half2_rn(v.x, v.y);
        reinterpret_cast<__half2*>(job.d)[2 * i + 1] = __floats2half2_rn(v.z, v.w);
    }
}

// ---------------- CSR build ----------------
__global__ void hist_kernel(const int* __restrict__ ei) {
    int e = blockIdx.x * blockDim.x + threadIdx.x;
    if (e < EE) atomicAdd(&g_deg[ei[EE + e]], 1);
}
__global__ void scanA_kernel() {
    int t = threadIdx.x, b = blockIdx.x;
    int idx = b * 1024 + t;
    int v = (idx < NN) ? g_deg[idx] : 0;
    int lane = t & 31, wid = t >> 5;
    int x = v;
#pragma unroll
    for (int o = 1; o < 32; o <<= 1) {
        int y = __shfl_up_sync(0xffffffffu, x, o);
        if (lane >= o) x += y;
    }
    __shared__ int wsum[32];
    if (lane == 31) wsum[wid] = x;
    __syncthreads();
    if (wid == 0) {
        int w = wsum[lane];
#pragma unroll
        for (int o = 1; o < 32; o <<= 1) {
            int y = __shfl_up_sync(0xffffffffu, w, o);
            if (lane >= o) w += y;
        }
        wsum[lane] = w;
    }
    __syncthreads();
    int incl = x + (wid > 0 ? wsum[wid - 1] : 0);
    if (idx < NN) g_rowptr[idx] = incl - v;
    if (t == 1023) g_blocksum[b] = incl;
}
__global__ void scanC_kernel() {
    __shared__ int base_s;
    if (threadIdx.x == 0) {
        int nb = blockIdx.x >> 2;
        int s = 0;
        for (int k = 0; k < nb; k++) s += g_blocksum[k];
        base_s = s;
    }
    __syncthreads();
    int i = blockIdx.x * 256 + threadIdx.x;
    if (i < NN) {
        int r = g_rowptr[i] + base_s;
        g_rowptr[i] = r;
        g_cursor[i] = r;
    }
    if (i == 0) g_rowptr[NN] = EE;
}
__global__ void fill_kernel(const int* __restrict__ ei) {
    int e = blockIdx.x * blockDim.x + threadIdx.x;
    if (e >= EE) return;
    int dst = ei[EE + e];
    int pos = atomicAdd(&g_cursor[dst], 1);
    g_ssrc[pos] = ei[e];
}

// ---------------- edge aggregation + LN1 + LN2 fused ----------------
// warp per dst: gout row accumulated in registers (never touches memory),
// then x2 = LN2(LN1(x + gout + skip) + tout) emitted fp32 + fp16.
__global__ void edge_ln_kernel(const float* __restrict__ x,
                               const float* __restrict__ ln1g, const float* __restrict__ ln1b,
                               const float* __restrict__ ln2g, const float* __restrict__ ln2b) {
    int row = (blockIdx.x * blockDim.x + threadIdx.x) >> 5;
    int lane = threadIdx.x & 31;
    if (row >= NN) return;
    const __half2* qr = reinterpret_cast<const __half2*>(g_qkv + (size_t)row * 1536);
    float4 q4[4];
#pragma unroll
    for (int h = 0; h < 4; h++) {
        float2 a = __half22float2(qr[h * 64 + lane * 2]);
        float2 b = __half22float2(qr[h * 64 + lane * 2 + 1]);
        q4[h] = make_float4(a.x, a.y, b.x, b.y);
    }

    float4 acc[4];
    float den[4];
#pragma unroll
    for (int h = 0; h < 4; h++) {
        acc[h] = make_float4(0.f, 0.f, 0.f, 0.f);
        den[h] = 0.f;
    }

    int p0 = g_rowptr[row], p1 = g_rowptr[row + 1];
    int nsrc = (p0 < p1) ? g_ssrc[p0] : 0;
    for (int p = p0; p < p1; p++) {
        int src = nsrc;
        if (p + 1 < p1) nsrc = g_ssrc[p + 1];
        const __half2* kr = reinterpret_cast<const __half2*>(
            g_qkv + (size_t)src * 1536 + 512);
        const __half2* vr = kr + 256;
        float s[4];
        float4 v4[4];
#pragma unroll
        for (int h = 0; h < 4; h++) {
            float2 ka = __half22float2(kr[h * 64 + lane * 2]);
            float2 kb = __half22float2(kr[h * 64 + lane * 2 + 1]);
            float2 va = __half22float2(vr[h * 64 + lane * 2]);
            float2 vb = __half22float2(vr[h * 64 + lane * 2 + 1]);
            v4[h] = make_float4(va.x, va.y, vb.x, vb.y);
            s[h] = q4[h].x * ka.x + q4[h].y * ka.y + q4[h].z * kb.x + q4[h].w * kb.y;
        }
#pragma unroll
        for (int h = 0; h < 4; h++)
#pragma unroll
            for (int o = 16; o > 0; o >>= 1)
                s[h] += __shfl_xor_sync(0xffffffffu, s[h], o);
#pragma unroll
        for (int h = 0; h < 4; h++) {
            float ex = expf(s[h] * 0.0883883476483184f);  // 1/sqrt(128)
            den[h] += ex;
            acc[h].x += ex * v4[h].x; acc[h].y += ex * v4[h].y;
            acc[h].z += ex * v4[h].z; acc[h].w += ex * v4[h].w;
        }
    }

    float4 o = make_float4(0.f, 0.f, 0.f, 0.f);
#pragma unroll
    for (int h = 0; h < 4; h++) {
        if (den[h] > 0.f) {
            float inv = 0.25f / den[h];
            o.x += acc[h].x * inv; o.y += acc[h].y * inv;
            o.z += acc[h].z * inv; o.w += acc[h].w * inv;
        }
    }

    // ---- fused LN1 + LN2 ----
    float4 xv = reinterpret_cast<const float4*>(x + (size_t)row * DD)[lane];
    float4 sv = reinterpret_cast<const float4*>(g_skip + (size_t)row * DD)[lane];
    float4 vv = make_float4(xv.x + sv.x + o.x, xv.y + sv.y + o.y,
                            xv.z + sv.z + o.z, xv.w + sv.w + o.w);
    float4 o1 = ln_core(vv, lane, ln1g, ln1b);
    const __half2* tr = reinterpret_cast<const __half2*>(g_toutf + (size_t)row * DD);
    float2 ta = __half22float2(tr[lane * 2]);
    float2 tb = __half22float2(tr[lane * 2 + 1]);
    float4 v2 = make_float4(o1.x + ta.x, o1.y + ta.y, o1.z + tb.x, o1.w + tb.y);
    float4 o2 = ln_core(v2, lane, ln2g, ln2b);
    reinterpret_cast<float4*>(g_x2 + (size_t)row * DD)[lane] = o2;
    size_t base = (size_t)row * DD + lane * 4;
    *reinterpret_cast<__half2*>(g_x2f + base)     = __floats2half2_rn(o2.x, o2.y);
    *reinterpret_cast<__half2*>(g_x2f + base + 2) = __floats2half2_rn(o2.z, o2.w);
}

// ---------------- fp16 mma.sync GEMM, 128x128 block tile ----------------
// OUT: 0=fp32 Cf; 1=fp16 Ch; 2=fp16+relu Ch; 3=mixed (q|k|v fp16 / skip fp32).
#define LDK 72
#define OA   0
#define OW   (128 * LDK * 2)          // 18432
#define STG    (OW + 128 * LDK * 2)   // 36864 per stage
#define SM_TOT (2 * STG)              // 73728 bytes

template<int OUT>
__global__ __launch_bounds__(256, 2) void gemm_fp16(
    const __half* __restrict__ A,
    const __half* __restrict__ W,
    const float* __restrict__ bias,
    float* __restrict__ Cf, __half* __restrict__ Ch,
    int M, int Nc, int K)
{
    extern __shared__ char smem[];
    const uint32_t smb = (uint32_t)__cvta_generic_to_shared(smem);

    const int tid  = threadIdx.x;
    const int lane = tid & 31;
    const int w    = tid >> 5;
    const int wm   = w & 3;
    const int wn   = w >> 2;
    const int bm   = blockIdx.y * 128;
    const int bn   = blockIdx.x * 128;

    const int lrow = lane & 7;
    const int quad = lane >> 3;
    const int a_roff = lrow + ((quad & 1) << 3);
    const int a_coff = (quad >> 1) << 3;
    const int b_roff = lrow + ((quad >> 1) << 3);
    const int b_coff = (quad & 1) << 3;

    float acc[2][8][4];
#pragma unroll
    for (int i = 0; i < 2; i++)
#pragma unroll
        for (int j = 0; j < 8; j++)
#pragma unroll
            for (int t = 0; t < 4; t++) acc[i][j][t] = 0.f;

    const int s_row = tid >> 3;
    const int s_c8  = (tid & 7) * 8;

    auto stage_fn = [&](int s, int k0) {
        uint32_t base = smb + s * STG;
#pragma unroll
        for (int it = 0; it < 4; it++) {
            int row = s_row + it * 32;
            int ga = bm + row; if (ga >= M) ga = M - 1;
            cp16(base + OA + (row * LDK + s_c8) * 2,
                 A + (size_t)ga * K + k0 + s_c8);
            cp16(base + OW + (row * LDK + s_c8) * 2,
                 W + (size_t)(bn + row) * K + k0 + s_c8);
        }
        asm volatile("cp.async.commit_group;");
    };

    const int nCh = K >> 6;
    stage_fn(0, 0);

    for (int c = 0; c < nCh; c++) {
        if (c + 1 < nCh) {
            stage_fn((c + 1) & 1, (c + 1) << 6);
            asm volatile("cp.async.wait_group 1;");
        } else {
            asm volatile("cp.async.wait_group 0;");
        }
        __syncthreads();

        uint32_t base = smb + (c & 1) * STG;
#pragma unroll
        for (int ks = 0; ks < 64; ks += 16) {
            uint32_t af[2][4], bf[8][2];
#pragma unroll
            for (int i = 0; i < 2; i++) {
                uint32_t off = (uint32_t)(((wm * 32 + i * 16 + a_roff) * LDK
                                           + ks + a_coff) * 2);
                ldsm_x4(af[i][0], af[i][1], af[i][2], af[i][3], base + OA + off);
            }
#pragma unroll
            for (int jp = 0; jp < 4; jp++) {
                uint32_t off = (uint32_t)(((wn * 64 + jp * 16 + b_roff) * LDK
                                           + ks + b_coff) * 2);
                ldsm_x4(bf[2 * jp][0], bf[2 * jp][1],
                        bf[2 * jp + 1][0], bf[2 * jp + 1][1],
                        base + OW + off);
            }
#pragma unroll
            for (int i = 0; i < 2; i++)
#pragma unroll
                for (int j = 0; j < 8; j++)
                    mma_f16(acc[i][j], af[i], bf[j]);
        }
        __syncthreads();
    }

    const int qr = lane >> 2;
    const int kq = (lane & 3) * 2;
#pragma unroll
    for (int i = 0; i < 2; i++) {
        int r0 = bm + wm * 32 + i * 16 + qr;
#pragma unroll
        for (int j = 0; j < 8; j++) {
            int c = bn + wn * 64 + j * 8 + kq;
            float b0 = bias[c], b1 = bias[c + 1];
            float v0 = acc[i][j][0] + b0, v1 = acc[i][j][1] + b1;
            float v2 = acc[i][j][2] + b0, v3 = acc[i][j][3] + b1;
            if (OUT == 2) {
                v0 = fmaxf(v0, 0.f); v1 = fmaxf(v1, 0.f);
                v2 = fmaxf(v2, 0.f); v3 = fmaxf(v3, 0.f);
            }
#pragma unroll
            for (int hrow = 0; hrow < 2; hrow++) {
                int r = r0 + hrow * 8;
                if (r >= M) continue;
                float va = hrow ? v2 : v0;
                float vb = hrow ? v3 : v1;
                if (OUT == 0) {
                    *reinterpret_cast<float2*>(Cf + (size_t)r * Nc + c) =
                        make_float2(va, vb);
                } else if (OUT == 1 || OUT == 2) {
                    *reinterpret_cast<__half2*>(Ch + (size_t)r * Nc + c) =
                        __floats2half2_rn(va, vb);
                } else { // OUT == 3
                    if (c < 1536)
                        *reinterpret_cast<__half2*>(Ch + (size_t)r * 1536 + c) =
                            __floats2half2_rn(va, vb);
                    else
                        *reinterpret_cast<float2*>(Cf + (size_t)r * DD + (c - 1536)) =
                            make_float2(va, vb);
                }
            }
        }
    }
}

// ---------------- ffn2 + LN3 fused: out = LN3(x2 + h @ W2^T + b2) ----------------
// Nc = 128 so the 128x128 tile spans full rows; LN done in-block via smem.
#define LDC 132   // padded fp32 row stride for epilogue staging

__global__ __launch_bounds__(256, 2) void gemm_ffn2_ln3(
    const __half* __restrict__ A,       // h [M, 512] fp16
    const __half* __restrict__ W,       // w2 [128, 512] fp16
    const float* __restrict__ bias,     // b2
    const float* __restrict__ x2,       // residual
    const float* __restrict__ ln3g, const float* __restrict__ ln3b,
    float* __restrict__ out, int M, int K)
{
    extern __shared__ char smem[];
    const uint32_t smb = (uint32_t)__cvta_generic_to_shared(smem);

    const int tid  = threadIdx.x;
    const int lane = tid & 31;
    const int w    = tid >> 5;
    const int wm   = w & 3;
    const int wn   = w >> 2;
    const int bm   = blockIdx.y * 128;

    const int lrow = lane & 7;
    const int quad = lane >> 3;
    const int a_roff = lrow + ((quad & 1) << 3);
    const int a_coff = (quad >> 1) << 3;
    const int b_roff = lrow + ((quad >> 1) << 3);
    const int b_coff = (quad & 1) << 3;

    float acc[2][8][4];
#pragma unroll
    for (int i = 0; i < 2; i++)
#pragma unroll
        for (int j = 0; j < 8; j++)
#pragma unroll
            for (int t = 0; t < 4; t++) acc[i][j][t] = 0.f;

    const int s_row = tid >> 3;
    const int s_c8  = (tid & 7) * 8;

    auto stage_fn = [&](int s, int k0) {
        uint32_t base = smb + s * STG;
#pragma unroll
        for (int it = 0; it < 4; it++) {
            int row = s_row + it * 32;
            int ga = bm + row; if (ga >= M) ga = M - 1;
            cp16(base + OA + (row * LDK + s_c8) * 2,
                 A + (size_t)ga * K + k0 + s_c8);
            cp16(base + OW + (row * LDK + s_c8) * 2,
                 W + (size_t)row * K + k0 + s_c8);
        }
        asm volatile("cp.async.commit_group;");
    };

    const int nCh = K >> 6;
    stage_fn(0, 0);

    for (int c = 0; c < nCh; c++) {
        if (c + 1 < nCh) {
            stage_fn((c + 1) & 1, (c + 1) << 6);
            asm volatile("cp.async.wait_group 1;");
        } else {
            asm volatile("cp.async.wait_group 0;");
        }
        __syncthreads();

        uint32_t base = smb + (c & 1) * STG;
#pragma unroll
        for (int ks = 0; ks < 64; ks += 16) {
            uint32_t af[2][4], bf[8][2];
#pragma unroll
            for (int i = 0; i < 2; i++) {
                uint32_t off = (uint32_t)(((wm * 32 + i * 16 + a_roff) * LDK
                                           + ks + a_coff) * 2);
                ldsm_x4(af[i][0], af[i][1], af[i][2], af[i][3], base + OA + off);
            }
#pragma unroll
            for (int jp = 0; jp < 4; jp++) {
                uint32_t off = (uint32_t)(((wn * 64 + jp * 16 + b_roff) * LDK
                                           + ks + b_coff) * 2);
                ldsm_x4(bf[2 * jp][0], bf[2 * jp][1],
                        bf[2 * jp + 1][0], bf[2 * jp + 1][1],
                        base + OW + off);
            }
#pragma unroll
            for (int i = 0; i < 2; i++)
#pragma unroll
                for (int j = 0; j < 8; j++)
                    mma_f16(acc[i][j], af[i], bf[j]);
        }
        __syncthreads();
    }

    // ---- epilogue: stage to smem (padded), then warp-per-row LN3 ----
    float* cs = reinterpret_cast<float*>(smem);   // 128 x LDC floats = 67584 B
    const int qr = lane >> 2;
    const int kq = (lane & 3) * 2;
#pragma unroll
    for (int i = 0; i < 2; i++) {
        int rl0 = wm * 32 + i * 16 + qr;
#pragma unroll
        for (int j = 0; j < 8; j++) {
            int c = wn * 64 + j * 8 + kq;
            float b0 = bias[c], b1 = bias[c + 1];
            cs[rl0 * LDC + c]           = acc[i][j][0] + b0;
            cs[rl0 * LDC + c + 1]       = acc[i][j][1] + b1;
            cs[(rl0 + 8) * LDC + c]     = acc[i][j][2] + b0;
            cs[(rl0 + 8) * LDC + c + 1] = acc[i][j][3] + b1;
        }
    }
    __syncthreads();
#pragma unroll
    for (int it = 0; it < 16; it++) {
        int rl = w * 16 + it;
        int r = bm + rl;
        if (r >= M) continue;
        const float* rowp = cs + rl * LDC;
        float4 fv = make_float4(rowp[lane * 4], rowp[lane * 4 + 1],
                                rowp[lane * 4 + 2], rowp[lane * 4 + 3]);
        float4 xv = reinterpret_cast<const float4*>(x2 + (size_t)r * DD)[lane];
        float4 vv = make_float4(fv.x + xv.x, fv.y + xv.y, fv.z + xv.z, fv.w + xv.w);
        float4 o = ln_core(vv, lane, ln3g, ln3b);
        reinterpret_cast<float4*>(out + (size_t)r * DD)[lane] = o;
    }
}

// ---------------- launch ----------------
static void* sym(const void* s) { void* p = nullptr; cudaGetSymbolAddress(&p, s); return p; }

extern "C" void kernel_launch(void* const* d_in, const int* in_sizes, int n_in,
                              void* d_out, int out_size)
{
    const float* x    = (const float*)d_in[0];
    const float* te   = (const float*)d_in[1];
    const float* gq_w = (const float*)d_in[2];  const float* gq_b = (const float*)d_in[3];
    const float* gk_w = (const float*)d_in[4];  const float* gk_b = (const float*)d_in[5];
    const float* gv_w = (const float*)d_in[6];  const float* gv_b = (const float*)d_in[7];
    const float* gs_w = (const float*)d_in[8];  const float* gs_b = (const float*)d_in[9];
    // mha_wq/bq, mha_wk/bk dead: softmax over one kv position is exactly 1.
    const float* wv   = (const float*)d_in[14]; const float* bv   = (const float*)d_in[15];
    const float* wo   = (const float*)d_in[16]; const float* bo   = (const float*)d_in[17];
    const float* w1   = (const float*)d_in[18]; const float* b1   = (const float*)d_in[19];
    const float* w2   = (const float*)d_in[20]; const float* b2   = (const float*)d_in[21];
    const float* ln1g = (const float*)d_in[22]; const float* ln1b = (const float*)d_in[23];
    const float* ln2g = (const float*)d_in[24]; const float* ln2b = (const float*)d_in[25];
    const float* ln3g = (const float*)d_in[26]; const float* ln3b = (const float*)d_in[27];
    const int*   ei   = (const int*)d_in[28];
    float* out = (float*)d_out;

    float* skip_p = (float*)sym(g_skip);
    float* x2_p   = (float*)sym(g_x2);
    float* bf_p   = (float*)sym(g_bias_f);
    float* wc_p   = (float*)sym(g_wc);
    float* bc_p   = (float*)sym(g_bc);

    __half* qkv_p  = (__half*)sym(g_qkv);
    __half* toutf  = (__half*)sym(g_toutf);
    __half* xf   = (__half*)sym(g_xf);
    __half* tef  = (__half*)sym(g_tef);
    __half* x2f  = (__half*)sym(g_x2f);
    __half* hf   = (__half*)sym(g_hf);
    __half* wf   = (__half*)sym(g_wf);
    __half* wcf  = (__half*)sym(g_wcf);
    __half* w1f  = (__half*)sym(g_w1f);
    __half* w2f  = (__half*)sym(g_w2f);

    cudaFuncSetAttribute(gemm_fp16<1>, cudaFuncAttributeMaxDynamicSharedMemorySize, SM_TOT);
    cudaFuncSetAttribute(gemm_fp16<2>, cudaFuncAttributeMaxDynamicSharedMemorySize, SM_TOT);
    cudaFuncSetAttribute(gemm_fp16<3>, cudaFuncAttributeMaxDynamicSharedMemorySize, SM_TOT);
    cudaFuncSetAttribute(gemm_ffn2_ln3, cudaFuncAttributeMaxDynamicSharedMemorySize, SM_TOT);

    const int MB = (NN + 127) / 128;       // 157
    const int NSCAN = (NN + 1023) / 1024;  // 20
    const int NB = (NN + 255) / 256;       // 79

    // setup (deg=0, bias concat) + temporal compose in one launch
    setup_compose<<<128 + NB, 256>>>(wo, wv, bv, bo, gq_b, gk_b, gv_b, gs_b);

    // CSR build
    hist_kernel<<<(EE + 255) / 256, 256>>>(ei);
    scanA_kernel<<<NSCAN, 1024>>>();
    scanC_kernel<<<(NN + 255) / 256, 256>>>();
    fill_kernel<<<(EE + 255) / 256, 256>>>(ei);

    AJs jobs;
    jobs.j[0] = {x,    xf,  NN * DD / 4};
    jobs.j[1] = {te,   tef, NN * DD / 4};
    jobs.j[2] = {gq_w, wf,              512 * 128 / 4};
    jobs.j[3] = {gk_w, wf + 512 * 128,  512 * 128 / 4};
    jobs.j[4] = {gv_w, wf + 1024 * 128, 512 * 128 / 4};
    jobs.j[5] = {gs_w, wf + 1536 * 128, 128 * 128 / 4};
    jobs.j[6] = {wc_p, wcf, 128 * 128 / 4};
    jobs.j[7] = {w1,   w1f, 512 * 128 / 4};
    jobs.j[8] = {w2,   w2f, 128 * 512 / 4};
    conv_a<<<dim3(64, 9), 256>>>(jobs);

    // fused q|k|v|skip projection: mixed output (q,k,v fp16; skip fp32)
    gemm_fp16<3><<<dim3(NFUSE / 128, MB), 256, SM_TOT>>>(
        xf, wf, bf_p, skip_p, qkv_p, NN, NFUSE, 128);
    // temporal (composed): tout = te @ Wc^T + bc  (fp16 out)
    gemm_fp16<1><<<dim3(1, MB), 256, SM_TOT>>>(
        tef, wcf, bc_p, nullptr, toutf, NN, 128, 128);

    // graph attention + LN1 + LN2 fused -> x2 (fp32 + fp16)
    edge_ln_kernel<<<(NN + 7) / 8, 256>>>(x, ln1g, ln1b, ln2g, ln2b);

    // FFN
    gemm_fp16<2><<<dim3(4, MB), 256, SM_TOT>>>(
        x2f, w1f, b1, nullptr, hf, NN, 512, 128);
    // ffn2 + LN3 fused -> out
    gemm_ffn2_ln3<<<dim3(1, MB), 256, SM_TOT>>>(
        hf, w2f, b2, x2_p, ln3g, ln3b, out, NN, 512);
}